// round 11
// baseline (speedup 1.0000x reference)
#include <cuda_runtime.h>
#include <math.h>

#define BATCH 64
#define SEQ   512
#define EMBED 256
#define HID   512
#define GD    768     // HID + EMBED
#define NCLS  4

#define NBLK  128     // 2 batch halves x 64 column groups
#define NTHR  256     // 8 warps
#define BG    32      // batch rows per CTA
#define ND    32      // dot-columns per CTA = 4 gates * 8 hidden units
#define K4T   192     // GD / 4 (float4 count per row)
#define HALF_CTAS 64

// SMEM: w[32][768] + inp[32][768] (XOR-swizzled) + 4 partial sets + bias
#define SM_W       0
#define SM_INP     (32*768)
#define SM_PART    (SM_INP + 32*768)
#define SET_STRIDE 1056                 // 32 cols' x 33 (row-padded)
#define SM_BIAS    (SM_PART + 4*SET_STRIDE)
#define SMEM_FLOATS (SM_BIAS + 32)
#define SMEM_BYTES  (SMEM_FLOATS * 4)   // ~213.7 KB

__device__ float g_h[2][BATCH*HID];
__device__ float g_maxh[BATCH*HID];
__device__ unsigned long long g_cnt;          // full-grid ticket counter
__device__ unsigned long long g_half[64];     // per-half counters (slots 0, 32)

__device__ __forceinline__ float sigf(float x)     { return 1.0f / (1.0f + __expf(-x)); }
__device__ __forceinline__ float tanhfast(float x) { return 2.0f / (1.0f + __expf(-2.0f*x)) - 1.0f; }

__device__ __forceinline__ void fma2(unsigned long long &d,
                                     unsigned long long a, unsigned long long b) {
    asm("fma.rn.f32x2 %0, %1, %2, %0;" : "+l"(d) : "l"(a), "l"(b));
}
__device__ __forceinline__ float sum2(unsigned long long v) {
    float lo, hi;
    asm("mov.b64 {%0,%1}, %2;" : "=f"(lo), "=f"(hi) : "l"(v));
    return lo + hi;
}

// cp.async 16B, L2-only (.cg): required for h (cross-SM coherence), fine for emb
__device__ __forceinline__ void cp16_cg(unsigned int saddr, const void* g) {
    asm volatile("cp.async.cg.shared.global [%0], [%1], 16;" :: "r"(saddr), "l"(g));
}
#define CP_COMMIT()  asm volatile("cp.async.commit_group;" ::: "memory")
#define CP_WAITALL() asm volatile("cp.async.wait_all;"     ::: "memory")

// Full-grid ticket barrier (fence-free; init and finish only).
__device__ __forceinline__ void ticket_barrier() {
    __syncthreads();
    if (threadIdx.x == 0) {
        unsigned long long ticket;
        asm volatile("atom.release.gpu.add.u64 %0, [%1], %2;"
                     : "=l"(ticket) : "l"(&g_cnt), "l"(1ULL) : "memory");
        unsigned long long target = (ticket / NBLK + 1ULL) * (unsigned long long)NBLK;
        unsigned long long cur;
        do {
            asm volatile("ld.acquire.gpu.u64 %0, [%1];"
                         : "=l"(cur) : "l"(&g_cnt) : "memory");
        } while (cur < target);
    }
    __syncthreads();
}

__device__ __forceinline__ void loadx(ulonglong2 xv[4], const float* xr0, int k4, int rg) {
    int ox = ((k4 ^ rg) << 2);
    #pragma unroll
    for (int r = 0; r < 4; r++)
        xv[r] = *(const ulonglong2*)(xr0 + r*GD + ox);
}

__device__ __forceinline__ void gemm_step4(unsigned long long acc[4][4],
                                           const ulonglong2 xv[4],
                                           const float* wc0, int k4, int kwbase) {
    #pragma unroll
    for (int c = 0; c < 4; c++) {
        int key = (kwbase + c) & 7;
        ulonglong2 wv = *(const ulonglong2*)(wc0 + c*GD + ((k4 ^ key) << 2));
        #pragma unroll
        for (int r = 0; r < 4; r++) {
            fma2(acc[r][c], xv[r].x, wv.x);
            fma2(acc[r][c], xv[r].y, wv.y);
        }
    }
}

extern "C" __global__ void __launch_bounds__(NTHR, 1)
lstm_persistent(const int*   __restrict__ ids,
                const float* __restrict__ emb,
                const float* __restrict__ Wf, const float* __restrict__ bf,
                const float* __restrict__ Wi, const float* __restrict__ bi,
                const float* __restrict__ Wo, const float* __restrict__ bo,
                const float* __restrict__ Wc, const float* __restrict__ bc,
                const float* __restrict__ fcw, const float* __restrict__ fcb,
                float* __restrict__ out)
{
    extern __shared__ float sm[];
    float* w_s    = sm + SM_W;
    float* inp_s  = sm + SM_INP;
    float* part_s = sm + SM_PART;
    float* bias_s = sm + SM_BIAS;

    const int tid  = threadIdx.x;
    const int cta  = blockIdx.x;
    const int half = cta & 1;
    const int b0   = half * BG;             // batch half
    const int j0   = (cta >> 1) * 8;        // hidden-unit group (8 units)
    const int wid  = tid >> 5;              // 0..7
    const int lane = tid & 31;

    unsigned long long* hctr = &g_half[half * 32];

    const float* Wg[4]  = {Wf, Wi, Wo, Wc};
    const float* bgp[4] = {bf, bi, bo, bc};

    // ---- one-time: weight slice into swizzled SMEM, key = ((d&15)+(d>>3))&7 ----
    for (int idx = tid; idx < ND*K4T; idx += NTHR) {
        int d  = idx / K4T;
        int k4 = idx - d*K4T;
        int g  = d >> 3, jj = d & 7;
        int key = ((d & 15) + (d >> 3)) & 7;
        float4 v = ((const float4*)(Wg[g] + (size_t)(j0 + jj) * GD))[k4];
        *(float4*)(w_s + d*GD + ((k4 ^ key) << 2)) = v;
    }
    if (tid < ND) {
        int g = tid >> 3, jj = tid & 7;
        bias_s[tid] = bgp[g][j0 + jj];
    }
    // zero the h(0) region this CTA owns
    if (tid < BG*8) {
        int r = tid >> 3, jj = tid & 7;
        g_h[0][(b0 + r)*HID + j0 + jj] = 0.0f;
    }

    // GEMM mapping: 8 warps = 4 K-segments x 2 col-halves; lane tile 4r x 4c
    const int kseg = wid & 3;                // 0..3
    const int ch   = wid >> 2;               // 0..1 -> cols 16ch..16ch+15
    const int kb   = kseg * 48;              // 4 segments x 48 k4
    const int rg   = lane >> 2;              // rows 4rg..4rg+3 (x key = rg)
    const int cg   = lane & 3;               // col group within half
    const int kwbase = 4*cg + (cg >> 1) + 2*ch;   // w key base; key_c = (kwbase+c)&7
    const float* xr0 = inp_s + (4*rg) * GD;
    const float* wc0 = w_s   + (16*ch + 4*cg) * GD;

    // partial-store indices: d = 16ch+4cg+c, idx(d) = 4(d&7)+(d>>3) (R6 layout)
    int pidx[4];
    #pragma unroll
    for (int c = 0; c < 4; c++) {
        int d = 16*ch + 4*cg + c;
        pidx[c] = (4*(d & 7) + (d >> 3))*33 + 4*rg;
    }

    // staging mapping: warp owns 4 rows stride 4
    const int dr    = lane >> 3;              // 0..3
    const int dk    = lane & 7;               // 0..7
    const int rbase = (wid & 3) + (wid >> 2) * 16;
    const int srow_ = rbase + 4*dr;
    const int ssw   = srow_ >> 2;
    float* sdst = inp_s + srow_ * GD;
    const unsigned int sdst_s = (unsigned int)__cvta_generic_to_shared(sdst);
    const int* idrow = ids + (b0 + srow_)*SEQ;

    // epilogue mapping: one thread per (batch row, hidden unit)
    const int eb  = tid >> 3;                 // 0..31
    const int ejj = tid & 7;                  // 0..7

    float cst  = 0.0f;
    float mmax = -INFINITY;

    // ---- pre-stage embedding for t=0 ----
    {
        int id0 = __ldg(idrow + 0);
        const float4* erow = (const float4*)(emb + (size_t)id0 * EMBED);
        #pragma unroll
        for (int o = 0; o < 8; o++) {
            int k4 = (16 + o)*8 + dk;
            *(float4*)(sdst + ((k4 ^ ssw) << 2)) = erow[o*8 + dk];
        }
    }

    unsigned long long hbase = *((volatile unsigned long long*)hctr);

    ticket_barrier();                          // h(0), emb(0), hbase settled

    for (int t = 0; t < SEQ; t++) {
        // ---- 1. stage h(t) via cp.async (.cg = L2-direct) ----
        {
            const float4* hrow = (const float4*)(g_h[t & 1] + (size_t)(b0 + srow_) * HID);
            #pragma unroll
            for (int oct = 0; oct < 16; oct++) {
                int k4 = oct*8 + dk;
                cp16_cg(sdst_s + ((k4 ^ ssw) << 4), hrow + k4);
            }
            CP_COMMIT();
        }
        CP_WAITALL();                          // h(this step) + emb(last step)
        __syncthreads();

        // ---- 2. register-tiled GEMM: 4x4 lane tile, 48 k4, double-buffered x ----
        unsigned long long acc[4][4];
        #pragma unroll
        for (int r = 0; r < 4; r++)
            #pragma unroll
            for (int c = 0; c < 4; c++) acc[r][c] = 0ULL;

        {
            ulonglong2 xa[4], xb[4];
            loadx(xa, xr0, kb, rg);
            #pragma unroll 4
            for (int kk = 0; kk < 48; kk += 2) {
                loadx(xb, xr0, kb + kk + 1, rg);
                gemm_step4(acc, xa, wc0, kb + kk, kwbase);
                if (kk + 2 < 48) loadx(xa, xr0, kb + kk + 2, rg);
                gemm_step4(acc, xb, wc0, kb + kk + 1, kwbase);
            }
        }

        // ---- 3. partial store (scalar, near-conflict-free) ----
        {
            float* myset = part_s + kseg*SET_STRIDE;
            #pragma unroll
            for (int c = 0; c < 4; c++)
                #pragma unroll
                for (int r = 0; r < 4; r++)
                    myset[pidx[c] + r] = sum2(acc[r][c]);
        }
        __syncthreads();

        const bool more = (t + 1 < SEQ);

        // ---- 4. emb(t+1) prefetch: cp.async, waited at next step top ----
        if (more) {
            int id1 = __ldg(idrow + t + 1);
            const float4* erow = (const float4*)(emb + (size_t)id1 * EMBED);
            #pragma unroll
            for (int o = 0; o < 8; o++) {
                int k4 = (16 + o)*8 + dk;
                cp16_cg(sdst_s + ((k4 ^ ssw) << 4), erow + o*8 + dk);
            }
            CP_COMMIT();
        }

        // ---- 5. epilogue: sum 4 segments, gates, state update, h store ----
        {
            float pf = bias_s[ 0 + ejj];
            float pi = bias_s[ 8 + ejj];
            float po = bias_s[16 + ejj];
            float pg = bias_s[24 + ejj];
            #pragma unroll
            for (int s = 0; s < 4; s++) {
                const float* sp = part_s + s*SET_STRIDE + eb;
                pf += sp[(4*ejj + 0)*33];
                pi += sp[(4*ejj + 1)*33];
                po += sp[(4*ejj + 2)*33];
                pg += sp[(4*ejj + 3)*33];
            }
            float f  = sigf(pf);
            float iv = sigf(pi);
            float o  = sigf(po);
            float gg = tanhfast(pg);
            cst = f*cst + iv*gg;
            float h = o * tanhfast(cst);
            mmax = fmaxf(mmax, h);
            g_h[(t + 1) & 1][(size_t)(b0 + eb)*HID + j0 + ejj] = h;
        }

        // ---- 6. half barrier: tid0 arrives, EVERY warp polls independently ----
        if (more) {
            __syncthreads();                   // all h stores done (CTA)
            if (tid == 0)
                asm volatile("red.release.gpu.add.u64 [%0], %1;"
                             :: "l"(hctr), "l"(1ULL) : "memory");
            unsigned long long target =
                hbase + (unsigned long long)HALF_CTAS * (t + 1);
            unsigned long long cur;
            do {
                asm volatile("ld.acquire.gpu.u64 %0, [%1];"
                             : "=l"(cur) : "l"(hctr) : "memory");
            } while (cur < target);
            // no block sync: each warp proceeds to its own staging
        }
    }

    // ---- max-over-time out, then tiny FC on CTA 0 ----
    g_maxh[(size_t)(b0 + eb)*HID + j0 + ejj] = mmax;
    ticket_barrier();

    if (cta == 0) {
        int b  = tid >> 2;
        int ci = tid & 3;
        const float4* a4 = (const float4*)(g_maxh + (size_t)b * HID);
        const float4* w4 = (const float4*)(fcw + (size_t)ci * HID);
        float acc0 = fcb[ci];
        #pragma unroll 4
        for (int k = 0; k < HID/4; k++) {
            float4 a = __ldcg(a4 + k);
            float4 w = w4[k];
            acc0 += a.x*w.x + a.y*w.y + a.z*w.z + a.w*w.w;
        }
        out[b*NCLS + ci] = acc0;
    }
}

extern "C" void kernel_launch(void* const* d_in, const int* in_sizes, int n_in,
                              void* d_out, int out_size)
{
    const int*   ids = (const int*)  d_in[0];
    const float* emb = (const float*)d_in[1];
    const float* Wf  = (const float*)d_in[2];
    const float* bf  = (const float*)d_in[3];
    const float* Wi  = (const float*)d_in[4];
    const float* bi  = (const float*)d_in[5];
    const float* Wo  = (const float*)d_in[6];
    const float* bo  = (const float*)d_in[7];
    const float* Wc  = (const float*)d_in[8];
    const float* bc  = (const float*)d_in[9];
    const float* fcw = (const float*)d_in[10];
    const float* fcb = (const float*)d_in[11];
    float* out = (float*)d_out;

    cudaFuncSetAttribute(lstm_persistent,
                         cudaFuncAttributeMaxDynamicSharedMemorySize, SMEM_BYTES);
    lstm_persistent<<<NBLK, NTHR, SMEM_BYTES>>>(ids, emb, Wf, bf, Wi, bi,
                                                Wo, bo, Wc, bc, fcw, fcb, out);
}

// round 12
// speedup vs baseline: 1.0634x; 1.0634x over previous
#include <cuda_runtime.h>
#include <math.h>

#define BATCH 64
#define SEQ   512
#define EMBED 256
#define HID   512
#define GD    768     // HID + EMBED
#define NCLS  4

#define NBLK  128     // 2 batch halves x 64 column groups
#define NTHR  256     // 8 warps
#define BG    32      // batch rows per CTA
#define ND    32      // dot-columns per CTA = 4 gates * 8 hidden units
#define K4T   192     // GD / 4 (float4 count per row)
#define HALF_CTAS 64

// SMEM: w[32][768] + inp[32][768] (XOR-swizzled) + 8 partial sets + bias
#define SM_W       0
#define SM_INP     (32*768)
#define SM_PART    (SM_INP + 32*768)
#define SET_STRIDE 1056                 // 32 cols' x 33 (row-padded)
#define SM_BIAS    (SM_PART + 8*SET_STRIDE)
#define SMEM_FLOATS (SM_BIAS + 32)
#define SMEM_BYTES  (SMEM_FLOATS * 4)   // 230,528 B

__device__ float g_h[2][BATCH*HID];
__device__ float g_maxh[BATCH*HID];
__device__ unsigned long long g_cnt;          // full-grid ticket counter
__device__ unsigned long long g_half[64];     // per-half counters (slots 0, 32)

__device__ __forceinline__ float sigf(float x)     { return 1.0f / (1.0f + __expf(-x)); }
__device__ __forceinline__ float tanhfast(float x) { return 2.0f / (1.0f + __expf(-2.0f*x)) - 1.0f; }

__device__ __forceinline__ void fma2(unsigned long long &d,
                                     unsigned long long a, unsigned long long b) {
    asm("fma.rn.f32x2 %0, %1, %2, %0;" : "+l"(d) : "l"(a), "l"(b));
}
__device__ __forceinline__ void mul2(unsigned long long &d,
                                     unsigned long long a, unsigned long long b) {
    asm("mul.rn.f32x2 %0, %1, %2;" : "=l"(d) : "l"(a), "l"(b));
}
__device__ __forceinline__ float sum2(unsigned long long v) {
    float lo, hi;
    asm("mov.b64 {%0,%1}, %2;" : "=f"(lo), "=f"(hi) : "l"(v));
    return lo + hi;
}

// cp.async 16B, L2-only (.cg): required for h (cross-SM coherence), fine for emb
__device__ __forceinline__ void cp16_cg(unsigned int saddr, const void* g) {
    asm volatile("cp.async.cg.shared.global [%0], [%1], 16;" :: "r"(saddr), "l"(g));
}
#define CP_COMMIT()    asm volatile("cp.async.commit_group;" ::: "memory")
#define CP_WAITALL()   asm volatile("cp.async.wait_all;"     ::: "memory")
#define CP_WAIT_ONE()  asm volatile("cp.async.wait_group 1;" ::: "memory")

// Full-grid ticket barrier (fence-free; init and finish only).
__device__ __forceinline__ void ticket_barrier() {
    __syncthreads();
    if (threadIdx.x == 0) {
        unsigned long long ticket;
        asm volatile("atom.release.gpu.add.u64 %0, [%1], %2;"
                     : "=l"(ticket) : "l"(&g_cnt), "l"(1ULL) : "memory");
        unsigned long long target = (ticket / NBLK + 1ULL) * (unsigned long long)NBLK;
        unsigned long long cur;
        do {
            asm volatile("ld.acquire.gpu.u64 %0, [%1];"
                         : "=l"(cur) : "l"(&g_cnt) : "memory");
        } while (cur < target);
    }
    __syncthreads();
}

// Per-half barrier: no-return release reduction + acquire poll vs per-replay base.
__device__ __forceinline__ void half_barrier(unsigned long long* ctr,
                                             unsigned long long target) {
    __syncthreads();
    if (threadIdx.x == 0) {
        asm volatile("red.release.gpu.add.u64 [%0], %1;"
                     :: "l"(ctr), "l"(1ULL) : "memory");
        unsigned long long cur;
        do {
            asm volatile("ld.acquire.gpu.u64 %0, [%1];"
                         : "=l"(cur) : "l"(ctr) : "memory");
        } while (cur < target);
    }
    __syncthreads();
}

extern "C" __global__ void __launch_bounds__(NTHR, 1)
lstm_persistent(const int*   __restrict__ ids,
                const float* __restrict__ emb,
                const float* __restrict__ Wf, const float* __restrict__ bf,
                const float* __restrict__ Wi, const float* __restrict__ bi,
                const float* __restrict__ Wo, const float* __restrict__ bo,
                const float* __restrict__ Wc, const float* __restrict__ bc,
                const float* __restrict__ fcw, const float* __restrict__ fcb,
                float* __restrict__ out)
{
    extern __shared__ float sm[];
    float* w_s    = sm + SM_W;
    float* inp_s  = sm + SM_INP;
    float* part_s = sm + SM_PART;
    float* bias_s = sm + SM_BIAS;

    const int tid  = threadIdx.x;
    const int cta  = blockIdx.x;
    const int half = cta & 1;
    const int b0   = half * BG;             // batch half
    const int j0   = (cta >> 1) * 8;        // hidden-unit group (8 units)
    const int wid  = tid >> 5;              // 0..7
    const int lane = tid & 31;

    unsigned long long* hctr = &g_half[half * 32];

    const float* Wg[4]  = {Wf, Wi, Wo, Wc};
    const float* bgp[4] = {bf, bi, bo, bc};

    // ---- one-time: weight slice into swizzled SMEM (key (d>>2)&7) ----
    for (int idx = tid; idx < ND*K4T; idx += NTHR) {
        int d  = idx / K4T;
        int k4 = idx - d*K4T;
        int g  = d >> 3, jj = d & 7;
        float4 v = ((const float4*)(Wg[g] + (size_t)(j0 + jj) * GD))[k4];
        *(float4*)(w_s + d*GD + ((k4 ^ ((d >> 2) & 7)) << 2)) = v;
    }
    if (tid < ND) {
        int g = tid >> 3, jj = tid & 7;
        bias_s[tid] = bgp[g][j0 + jj];
    }
    // zero the h(0) region this CTA owns
    if (tid < BG*8) {
        int r = tid >> 3, jj = tid & 7;
        g_h[0][(b0 + r)*HID + j0 + jj] = 0.0f;
    }

    // GEMM mapping: 8 warps, lane tile 4 rows x 8 cols
    // h-part:   kbh = wid*16      (16 k4, K 0..511)
    // emb-part: kbe = 128 + wid*8 ( 8 k4, K 512..767)
    const int rg  = lane >> 2;               // rows 4rg..4rg+3 (x key = rg)
    const int cg  = lane & 3;                // cols 8cg..8cg+7
    const int kbh = wid * 16;
    const int kbe = 128 + wid * 8;
    const int s0  = (2*cg) & 7;              // w key, cols 8cg..8cg+3
    const int s1  = (2*cg + 1) & 7;          // w key, cols 8cg+4..8cg+7
    const float* xr0 = inp_s + (4*rg) * GD;
    const float* wc0 = w_s   + (8*cg) * GD;

    // staging mapping: warp owns 4 rows stride 4
    const int dr    = lane >> 3;              // 0..3
    const int dk    = lane & 7;               // 0..7
    const int rbase = (wid & 3) + (wid >> 2) * 16;
    const int srow_ = rbase + 4*dr;
    const int ssw   = srow_ >> 2;
    float* sdst = inp_s + srow_ * GD;
    const unsigned int sdst_s = (unsigned int)__cvta_generic_to_shared(sdst);
    const int* idrow = ids + (b0 + srow_)*SEQ;

    // epilogue mapping: one thread per (batch row, hidden unit)
    const int eb  = tid >> 3;                 // 0..31
    const int ejj = tid & 7;                  // 0..7

    float cst  = 0.0f;
    float mmax = -INFINITY;

    // ---- pre-stage embedding for t=0 ----
    {
        int id0 = __ldg(idrow + 0);
        const float4* erow = (const float4*)(emb + (size_t)id0 * EMBED);
        #pragma unroll
        for (int o = 0; o < 8; o++) {
            int k4 = (16 + o)*8 + dk;
            *(float4*)(sdst + ((k4 ^ ssw) << 2)) = erow[o*8 + dk];
        }
    }

    unsigned long long hbase = *((volatile unsigned long long*)hctr);

    ticket_barrier();                          // h(0), emb(0), hbase settled

    for (int t = 0; t < SEQ; t++) {
        // ---- 1. issue h(t) staging (cp.async .cg, group: "h") ----
        {
            const float4* hrow = (const float4*)(g_h[t & 1] + (size_t)(b0 + srow_) * HID);
            #pragma unroll
            for (int oct = 0; oct < 16; oct++) {
                int k4 = oct*8 + dk;
                cp16_cg(sdst_s + ((k4 ^ ssw) << 4), hrow + k4);
            }
            CP_COMMIT();
        }

        // ---- 2. emb(t) group complete (h may still be in flight) ----
        CP_WAIT_ONE();
        __syncthreads();                       // emb visible CTA-wide

        // ---- 3. emb-part GEMM while h(t) lands (init acc via mul2) ----
        unsigned long long acc[4][8];
        #pragma unroll
        for (int kk = 0; kk < 8; kk++) {
            int k4 = kbe + kk;
            int ox = ((k4 ^ rg) << 2);
            int o0 = ((k4 ^ s0) << 2), o1 = ((k4 ^ s1) << 2);
            ulonglong2 xv[4], wv[8];
            #pragma unroll
            for (int r = 0; r < 4; r++)
                xv[r] = *(const ulonglong2*)(xr0 + r*GD + ox);
            #pragma unroll
            for (int c = 0; c < 8; c++)
                wv[c] = *(const ulonglong2*)(wc0 + c*GD + (c < 4 ? o0 : o1));
            if (kk == 0) {
                #pragma unroll
                for (int c = 0; c < 8; c++)
                    #pragma unroll
                    for (int r = 0; r < 4; r++) {
                        mul2(acc[r][c], xv[r].x, wv[c].x);
                        fma2(acc[r][c], xv[r].y, wv[c].y);
                    }
            } else {
                #pragma unroll
                for (int c = 0; c < 8; c++)
                    #pragma unroll
                    for (int r = 0; r < 4; r++) {
                        fma2(acc[r][c], xv[r].x, wv[c].x);
                        fma2(acc[r][c], xv[r].y, wv[c].y);
                    }
            }
        }

        // ---- 4. h(t) landed; h-part GEMM (batched loads per k4) ----
        CP_WAITALL();
        __syncthreads();
        #pragma unroll 2
        for (int kk = 0; kk < 16; kk++) {
            int k4 = kbh + kk;
            int ox = ((k4 ^ rg) << 2);
            int o0 = ((k4 ^ s0) << 2), o1 = ((k4 ^ s1) << 2);
            ulonglong2 xv[4], wv[8];
            #pragma unroll
            for (int r = 0; r < 4; r++)
                xv[r] = *(const ulonglong2*)(xr0 + r*GD + ox);
            #pragma unroll
            for (int c = 0; c < 8; c++)
                wv[c] = *(const ulonglong2*)(wc0 + c*GD + (c < 4 ? o0 : o1));
            #pragma unroll
            for (int c = 0; c < 8; c++)
                #pragma unroll
                for (int r = 0; r < 4; r++) {
                    fma2(acc[r][c], xv[r].x, wv[c].x);
                    fma2(acc[r][c], xv[r].y, wv[c].y);
                }
        }

        // ---- 5. partial store (scalar, conflict-free: bank = col'+row) ----
        {
            float* myset = part_s + wid*SET_STRIDE;
            #pragma unroll
            for (int c = 0; c < 8; c++)
                #pragma unroll
                for (int r = 0; r < 4; r++)
                    myset[(4*c + cg)*33 + 4*rg + r] = sum2(acc[r][c]);
        }
        __syncthreads();

        const bool more = (t + 1 < SEQ);

        // ---- 6. emb(t+1) prefetch (group: "emb", waited at next step top) ----
        if (more) {
            int id1 = __ldg(idrow + t + 1);
            const float4* erow = (const float4*)(emb + (size_t)id1 * EMBED);
            #pragma unroll
            for (int o = 0; o < 8; o++) {
                int k4 = (16 + o)*8 + dk;
                cp16_cg(sdst_s + ((k4 ^ ssw) << 4), erow + o*8 + dk);
            }
            CP_COMMIT();
        }

        // ---- 7. epilogue: sum 8 segments, gates, state update, h store ----
        {
            float pf = bias_s[ 0 + ejj];
            float pi = bias_s[ 8 + ejj];
            float po = bias_s[16 + ejj];
            float pg = bias_s[24 + ejj];
            #pragma unroll
            for (int s = 0; s < 8; s++) {
                const float* sp = part_s + s*SET_STRIDE + eb;
                pf += sp[(4*ejj + 0)*33];
                pi += sp[(4*ejj + 1)*33];
                po += sp[(4*ejj + 2)*33];
                pg += sp[(4*ejj + 3)*33];
            }
            float f  = sigf(pf);
            float iv = sigf(pi);
            float o  = sigf(po);
            float gg = tanhfast(pg);
            cst = f*cst + iv*gg;
            float h = o * tanhfast(cst);
            mmax = fmaxf(mmax, h);
            g_h[(t + 1) & 1][(size_t)(b0 + eb)*HID + j0 + ejj] = h;
        }

        // ---- 8. 64-CTA half barrier (skip after the last step) ----
        if (more)
            half_barrier(hctr, hbase + (unsigned long long)HALF_CTAS * (t + 1));
    }

    // ---- max-over-time out, then tiny FC on CTA 0 ----
    g_maxh[(size_t)(b0 + eb)*HID + j0 + ejj] = mmax;
    ticket_barrier();

    if (cta == 0) {
        int b  = tid >> 2;
        int ci = tid & 3;
        const float4* a4 = (const float4*)(g_maxh + (size_t)b * HID);
        const float4* w4 = (const float4*)(fcw + (size_t)ci * HID);
        float acc0 = fcb[ci];
        #pragma unroll 4
        for (int k = 0; k < HID/4; k++) {
            float4 a = __ldcg(a4 + k);
            float4 w = w4[k];
            acc0 += a.x*w.x + a.y*w.y + a.z*w.z + a.w*w.w;
        }
        out[b*NCLS + ci] = acc0;
    }
}

extern "C" void kernel_launch(void* const* d_in, const int* in_sizes, int n_in,
                              void* d_out, int out_size)
{
    const int*   ids = (const int*)  d_in[0];
    const float* emb = (const float*)d_in[1];
    const float* Wf  = (const float*)d_in[2];
    const float* bf  = (const float*)d_in[3];
    const float* Wi  = (const float*)d_in[4];
    const float* bi  = (const float*)d_in[5];
    const float* Wo  = (const float*)d_in[6];
    const float* bo  = (const float*)d_in[7];
    const float* Wc  = (const float*)d_in[8];
    const float* bc  = (const float*)d_in[9];
    const float* fcw = (const float*)d_in[10];
    const float* fcb = (const float*)d_in[11];
    float* out = (float*)d_out;

    cudaFuncSetAttribute(lstm_persistent,
                         cudaFuncAttributeMaxDynamicSharedMemorySize, SMEM_BYTES);
    lstm_persistent<<<NBLK, NTHR, SMEM_BYTES>>>(ids, emb, Wf, bf, Wi, bi,
                                                Wo, bo, Wc, bc, fcw, fcb, out);
}